// round 5
// baseline (speedup 1.0000x reference)
#include <cuda_runtime.h>
#include <math.h>

#define L_LAYERS 32
#define BEAM 8
#define KV2 2
#define HEADS 8
#define SEQ 1024
#define HDIM 64
#define VOCAB 50257
#define HIST 128
#define TOPK 8
#define CHUNKS 32
#define CHUNK_SZ 1571          // 32*1571 = 50272 >= 50257

// per-(l,b) slab: KV2*HEADS*SEQ*HDIM floats = 1,048,576 floats = 262,144 float4
#define SLAB_F4 262144
#define NUM_SLABS (L_LAYERS * BEAM)          // 256

// output offsets (float32 elements, concatenated in reference return order)
#define OFF_KV   0LL
#define OFF_SAVE 268435456LL
#define OFF_PROB 268436488LL
#define OFF_TBI  268436496LL
#define OFF_MAX  268436504LL

// device-global scratch (no allocations allowed)
__device__ float g_part_m[BEAM * CHUNKS];
__device__ float g_part_s[BEAM * CHUNKS];
__device__ float g_part_val[BEAM * CHUNKS * TOPK];
__device__ int   g_part_idx[BEAM * CHUNKS * TOPK];
__device__ int   g_beam_index[BEAM];

__device__ __forceinline__ bool cand_gt(float av, int ai, float bv, int bi) {
    // strictly greater value wins; on exact tie, lower index wins (jax.lax.top_k order)
    return (av > bv) || (av == bv && ai < bi);
}

// ---------------------------------------------------------------------------
// Kernel 1: per-chunk online softmax (m, s) + top-8.
// grid = BEAM*CHUNKS = 256 blocks, 128 threads. Single pass over the data.
// ---------------------------------------------------------------------------
__global__ void __launch_bounds__(128) chunk_topk_kernel(const float* __restrict__ logits) {
    const int chunk = blockIdx.x & (CHUNKS - 1);
    const int r     = blockIdx.x >> 5;
    const int tid   = threadIdx.x;
    const int start = chunk * CHUNK_SZ;
    const int end   = min(start + CHUNK_SZ, VOCAB);
    const float* row = logits + (long long)r * VOCAB;

    // thread-local online softmax + sorted top-8
    float m = -INFINITY, s = 0.0f;
    float lv[TOPK];
    int   li[TOPK];
#pragma unroll
    for (int j = 0; j < TOPK; j++) { lv[j] = -INFINITY; li[j] = 0x7fffffff; }

    for (int i = start + tid; i < end; i += 128) {
        float v = row[i];
        // online softmax
        if (v > m) { s = s * __expf(m - v) + 1.0f; m = v; }
        else       { s += __expf(v - m); }
        // top-8 insertion
        if (cand_gt(v, i, lv[TOPK - 1], li[TOPK - 1])) {
            int j = TOPK - 1;
            while (j > 0 && cand_gt(v, i, lv[j - 1], li[j - 1])) {
                lv[j] = lv[j - 1]; li[j] = li[j - 1]; j--;
            }
            lv[j] = v; li[j] = i;
        }
    }

    // block reduce (m, s) pairs
    __shared__ float sm[128], ss[128];
    sm[tid] = m; ss[tid] = s;
    __syncthreads();
    for (int st = 64; st > 0; st >>= 1) {
        if (tid < st) {
            float m1 = sm[tid], s1 = ss[tid];
            float m2 = sm[tid + st], s2 = ss[tid + st];
            float M = fmaxf(m1, m2);
            // guard -inf - -inf
            float S = ((m1 > -INFINITY) ? s1 * __expf(m1 - M) : 0.0f)
                    + ((m2 > -INFINITY) ? s2 * __expf(m2 - M) : 0.0f);
            sm[tid] = M; ss[tid] = S;
        }
        __syncthreads();
    }

    // tree-merge 128 sorted 8-lists -> chunk top-8
    __shared__ float sv[128 * TOPK];
    __shared__ int   si[128 * TOPK];
#pragma unroll
    for (int j = 0; j < TOPK; j++) { sv[tid * TOPK + j] = lv[j]; si[tid * TOPK + j] = li[j]; }
    __syncthreads();

    for (int step = 1; step < 128; step <<= 1) {
        if ((tid & (2 * step - 1)) == 0) {
            float* A  = &sv[tid * TOPK];
            int*   Ai = &si[tid * TOPK];
            float* B  = &sv[(tid + step) * TOPK];
            int*   Bi = &si[(tid + step) * TOPK];
            float mv[TOPK]; int mi[TOPK];
            int pa = 0, pb = 0;
#pragma unroll
            for (int j = 0; j < TOPK; j++) {
                if (cand_gt(A[pa], Ai[pa], B[pb], Bi[pb])) { mv[j] = A[pa]; mi[j] = Ai[pa]; pa++; }
                else                                        { mv[j] = B[pb]; mi[j] = Bi[pb]; pb++; }
            }
#pragma unroll
            for (int j = 0; j < TOPK; j++) { A[j] = mv[j]; Ai[j] = mi[j]; }
        }
        __syncthreads();
    }

    if (tid == 0) {
        g_part_m[blockIdx.x] = sm[0];
        g_part_s[blockIdx.x] = ss[0];
    }
    if (tid < TOPK) {
        g_part_val[blockIdx.x * TOPK + tid] = sv[tid];
        g_part_idx[blockIdx.x * TOPK + tid] = si[tid];
    }
}

// ---------------------------------------------------------------------------
// Kernel 2: per-row merge (LSE + top-8), global beam top-8, small outputs.
// One block, 256 threads.
// ---------------------------------------------------------------------------
__global__ void select_kernel(const int* __restrict__ save_id,
                              const float* __restrict__ prev_prob,
                              float* __restrict__ out) {
    __shared__ float cv[BEAM * TOPK];   // candidate values (prob-adjusted)
    __shared__ int   ci[BEAM * TOPK];   // candidate vocab indices
    __shared__ int   s_beam[BEAM];
    __shared__ int   s_tbi[BEAM];
    __shared__ float s_prob[BEAM];

    const int tid = threadIdx.x;

    // one thread per row: combine 32 (m,s) -> lse; top-8 of 256 partial cands
    if (tid < BEAM) {
        const int r = tid;
        float M = -INFINITY;
        for (int c = 0; c < CHUNKS; c++) M = fmaxf(M, g_part_m[r * CHUNKS + c]);
        float S = 0.0f;
        for (int c = 0; c < CHUNKS; c++) {
            float pm = g_part_m[r * CHUNKS + c];
            if (pm > -INFINITY) S += g_part_s[r * CHUNKS + c] * __expf(pm - M);
        }
        const float lse = M + logf(S);

        const float* pv = &g_part_val[r * CHUNKS * TOPK];
        const int*   pi = &g_part_idx[r * CHUNKS * TOPK];
        int chosen[TOPK];
        for (int k = 0; k < TOPK; k++) {
            int best = -1;
            float bv = -INFINITY; int bidx = 0x7fffffff;
            for (int i = 0; i < CHUNKS * TOPK; i++) {
                bool skip = false;
                for (int p = 0; p < k; p++) if (chosen[p] == i) { skip = true; break; }
                if (skip) continue;
                if (best < 0 || cand_gt(pv[i], pi[i], bv, bidx)) {
                    best = i; bv = pv[i]; bidx = pi[i];
                }
            }
            chosen[k] = best;
            cv[r * TOPK + k] = bv - lse + prev_prob[r];
            ci[r * TOPK + k] = bidx;
        }
    }
    __syncthreads();

    if (tid == 0) {
        bool used[BEAM * TOPK];
        for (int i = 0; i < BEAM * TOPK; i++) used[i] = false;
        for (int b = 0; b < BEAM; b++) {
            int best = -1;
            for (int i = 0; i < BEAM * TOPK; i++) {
                if (used[i]) continue;
                if (best < 0 || cv[i] > cv[best]) best = i;  // strict > keeps lower flat index
            }
            used[best] = true;
            s_beam[b] = best >> 3;
            s_tbi[b]  = ci[best];
            s_prob[b] = cv[best];
            g_beam_index[b] = best >> 3;
        }
    }
    __syncthreads();

    // new_save_id: [8, 129] = gathered save_id concat tbi
    for (int i = tid; i < BEAM * (HIST + 1); i += blockDim.x) {
        int b = i / (HIST + 1);
        int c = i % (HIST + 1);
        int val = (c < HIST) ? save_id[s_beam[b] * HIST + c] : s_tbi[b];
        out[OFF_SAVE + i] = (float)val;
    }
    if (tid < BEAM) {
        out[OFF_PROB + tid] = s_prob[tid];
        out[OFF_TBI + tid]  = (float)s_tbi[tid];
    }
    if (tid == 0) out[OFF_MAX] = (float)s_tbi[0];
}

// ---------------------------------------------------------------------------
// Kernel 3: kv_cache gather along the beam axis. float4 streaming copy.
// ---------------------------------------------------------------------------
__global__ void gather_kernel(const float4* __restrict__ kv,
                              float4* __restrict__ out) {
    __shared__ int bi[BEAM];
    if (threadIdx.x < BEAM) bi[threadIdx.x] = g_beam_index[threadIdx.x];
    __syncthreads();

    const int slab        = blockIdx.x >> 8;
    const int blk_in_slab = blockIdx.x & 255;
    const int b = slab & 7;
    const int l = slab >> 3;

    const long long src_base = (long long)(l * BEAM + bi[b]) * SLAB_F4;
    const long long dst_base = (long long)slab * SLAB_F4;
    const int off = blk_in_slab * 1024 + threadIdx.x;

#pragma unroll
    for (int i = 0; i < 4; i++) {
        out[dst_base + off + i * 256] = kv[src_base + off + i * 256];
    }
}

// ---------------------------------------------------------------------------
extern "C" void kernel_launch(void* const* d_in, const int* in_sizes, int n_in,
                              void* d_out, int out_size) {
    const float* kv_cache  = (const float*)d_in[0];
    const float* logits    = (const float*)d_in[1];
    const int*   save_id   = (const int*)d_in[2];
    const float* prev_prob = (const float*)d_in[3];
    float* out = (float*)d_out;

    chunk_topk_kernel<<<BEAM * CHUNKS, 128>>>(logits);
    select_kernel<<<1, 256>>>(save_id, prev_prob, out);
    gather_kernel<<<NUM_SLABS * (SLAB_F4 / 1024), 256>>>(
        (const float4*)kv_cache, (float4*)(out + OFF_KV));
}